// round 13
// baseline (speedup 1.0000x reference)
#include <cuda_runtime.h>
#include <cuda_fp16.h>

#define KPS   39
#define DIN   78
#define DHID  195
#define TB    128      // tokens per tile
#define NT    256      // 8 warps, 16 tokens each

// uint offsets into dynamic smem
#define OFS_WS    0        // w1h frags 8000 u
#define OFS_W2    8000     // w2h frags 8320 u
#define OFS_JH    16320    // uint[128][44]  (= half[128][88]) : 5632 u
#define OFS_B1    21952    // 200 f
#define OFS_ALBE1 22152    // 400 f
#define OFS_B2    22552    // 80 f
#define OFS_ALBE2 22632    // 160 f
#define OFS_OSL   22792    // out slab: 8 warps x 8 rows x 84 f = 5376 f
#define SMEM_WORDS 28168   // 112672 bytes -> 2 CTAs/SM

#define JH_U  44           // uint stride per token row (88 halves)
#define OSL_S 84           // slab row stride (floats)

// fp16 weight fragment scratch (prepped once per launch), uint = fp16x2
__device__ unsigned g_w1h[8000];   // per kt(5): 12 nt-pairs [p][lane][4] + nt=24 [lane][2]
__device__ unsigned g_w2h[8320];   // per kt(13): 5 nt-pairs [p][lane][4]

__device__ __forceinline__ void mma_f16(float c[4],
                                        unsigned a0, unsigned a1, unsigned a2, unsigned a3,
                                        unsigned b0, unsigned b1) {
    asm volatile(
        "mma.sync.aligned.m16n8k16.row.col.f32.f16.f16.f32 "
        "{%0,%1,%2,%3}, {%4,%5,%6,%7}, {%8,%9}, {%0,%1,%2,%3};"
        : "+f"(c[0]), "+f"(c[1]), "+f"(c[2]), "+f"(c[3])
        : "r"(a0), "r"(a1), "r"(a2), "r"(a3), "r"(b0), "r"(b1));
}

__device__ __forceinline__ unsigned pack_h2(float lo, float hi) {
    __half2 h = __floats2half2_rn(lo, hi);
    return *(unsigned*)&h;
}

// ---------- prep: fp16-pack weights into mma fragment layout ----------
__global__ void prep_weights_kernel(const float* __restrict__ W1,
                                    const float* __restrict__ W2)
{
    int o = blockIdx.x * 256 + threadIdx.x;       // 0..16319
    if (o < 8000) {
        int kt  = o / 1600;
        int rem = o - kt * 1600;
        int n, kbase;
        if (rem < 1536) {
            int p    = rem >> 7;
            int q    = rem & 127;
            int lane = q >> 2, fi = q & 3;
            int gid = lane >> 2, tig = lane & 3;
            int nt  = 2 * p + (fi >> 1);
            n = nt * 8 + gid;
            kbase = kt * 16 + 2 * tig + 8 * (fi & 1);
        } else {
            int q    = rem - 1536;
            int lane = q >> 1, reg = q & 1;
            int gid = lane >> 2, tig = lane & 3;
            n = 192 + gid;
            kbase = kt * 16 + 2 * tig + 8 * reg;
        }
        float lo = (n < DHID && kbase     < DIN) ? W1[n * DIN + kbase]     : 0.f;
        float hi = (n < DHID && kbase + 1 < DIN) ? W1[n * DIN + kbase + 1] : 0.f;
        g_w1h[o] = pack_h2(lo, hi);
    } else if (o < 16320) {
        int o2  = o - 8000;
        int kt  = o2 / 640;
        int rem = o2 - kt * 640;
        int p    = rem >> 7;
        int q    = rem & 127;
        int lane = q >> 2, fi = q & 3;
        int gid = lane >> 2, tig = lane & 3;
        int nt  = 2 * p + (fi >> 1);
        int n = nt * 8 + gid;
        int kbase = kt * 16 + 2 * tig + 8 * (fi & 1);
        float lo = (n < DIN && kbase     < DHID) ? W2[n * DHID + kbase]     : 0.f;
        float hi = (n < DIN && kbase + 1 < DHID) ? W2[n * DHID + kbase + 1] : 0.f;
        g_w2h[o2] = pack_h2(lo, hi);
    }
}

// --------------------------------- main (persistent) ---------------------------------
__global__ __launch_bounds__(NT, 2)
void spatialctx_tc_kernel(
    const float* __restrict__ x, const float* __restrict__ y,
    const float* __restrict__ b1, const float* __restrict__ b2,
    const float* __restrict__ a1, const float* __restrict__ a2,
    const float* __restrict__ alpha1, const float* __restrict__ beta1,
    const float* __restrict__ alpha2, const float* __restrict__ beta2,
    float* __restrict__ out, int ntok, int ntiles)
{
    extern __shared__ unsigned smu[];
    unsigned* ws    = smu + OFS_WS;
    unsigned* w2s   = smu + OFS_W2;
    unsigned* jh    = smu + OFS_JH;
    float*    b1s   = (float*)(smu + OFS_B1);
    float2*   albe1 = (float2*)(smu + OFS_ALBE1);
    float*    b2s   = (float*)(smu + OFS_B2);
    float2*   albe2 = (float2*)(smu + OFS_ALBE2);
    float*    osl   = (float*)(smu + OFS_OSL);

    const int tid = threadIdx.x;

    // ---- prologue: stage both weight-fragment sets (once) ----
    {
        const float4* s1 = (const float4*)g_w1h;
        float4* d1 = (float4*)ws;
        #pragma unroll
        for (int i = 0; i < 8; i++) {
            int o = tid + i * NT;
            if (o < 2000) d1[o] = s1[o];
        }
        const float4* s2 = (const float4*)g_w2h;
        float4* d2 = (float4*)w2s;
        #pragma unroll
        for (int i = 0; i < 9; i++) {
            int o = tid + i * NT;
            if (o < 2080) d2[o] = s2[o];
        }
    }
    if (tid < 200) {
        b1s[tid] = (tid < DHID) ? b1[tid] : 0.f;
        albe1[tid] = make_float2((tid < DHID) ? alpha1[tid] : 0.f,
                                 (tid < DHID) ? beta1[tid]  : 0.f);
    }
    if (tid < 80) {
        b2s[tid] = (tid < DIN) ? b2[tid] : 0.f;
        albe2[tid] = make_float2((tid < DIN) ? alpha2[tid] : 0.f,
                                 (tid < DIN) ? beta2[tid]  : 0.f);
    }
    if (tid < 128) {       // zero the jh pad columns (words 39..43) once
        #pragma unroll
        for (int c = 39; c < 44; c++) jh[tid * JH_U + c] = 0u;
    }
    const float a1v = a1[0];
    const float a2v = a2[0];
    __syncthreads();       // the only block-wide barrier

    const int warp   = tid >> 5;
    const int lane   = tid & 31;
    const int r      = lane >> 2;
    const int tig    = lane & 3;
    const int tokrow = warp * 16;

    unsigned* jwu  = jh + tokrow * JH_U;            // warp-private rows
    float*    oslw = osl + warp * (8 * OSL_S);      // warp-private 8x84 slab

    // staging role: 2 lanes per token row, word-packed stores
    const int strow = lane >> 1;                    // 0..15
    const int spart = lane & 1;                     // word range [spart*20, +20)

    for (int tile = blockIdx.x; tile < ntiles; tile += gridDim.x) {
        const int tbase = tile * TB;
        const int gt0w  = tbase + tokrow;          // warp's first token

        // ---- stage warp's 16 token rows as packed fp16 words ----
        // same-warp program order makes prior-tile LDS vs these STS safe
        {
            const int gt = gt0w + strow;
            const bool ok = gt < ntok;
            const float* xr = x + (size_t)gt * KPS;
            const float* yr = y + (size_t)gt * KPS;
            unsigned* dst = jwu + strow * JH_U + spart * 20;
            #pragma unroll
            for (int j = 0; j < 20; j++) {
                int w  = spart * 20 + j;
                int d0 = 2 * w, d1 = d0 + 1;
                float lo = 0.f, hi = 0.f;
                if (ok && w < 39) {
                    lo = (d0 < KPS) ? xr[d0] : yr[d0 - KPS];
                    hi = (d1 < KPS) ? xr[d1] : yr[d1 - KPS];
                }
                dst[j] = pack_h2(lo, hi);          // w=39 rewrites pad with 0
            }
        }
        // ---- L2 prefetch of next tile's slabs ----
        {
            int ntile = tile + gridDim.x;
            if (ntile < ntiles && lane < 20) {
                const float* px = x + (size_t)(ntile * TB + tokrow) * KPS + lane * 32;
                const float* py = y + (size_t)(ntile * TB + tokrow) * KPS + lane * 32;
                asm volatile("prefetch.global.L2 [%0];" :: "l"(px));
                asm volatile("prefetch.global.L2 [%0];" :: "l"(py));
            }
        }
        __syncwarp();

        // ================= GEMM1: C[16tok x 200], 5 k-tiles ============
        float acc[25][4];
        #pragma unroll
        for (int nt = 0; nt < 25; nt++)
            #pragma unroll
            for (int i = 0; i < 4; i++) acc[nt][i] = 0.f;

        {
            const unsigned* ar0 = jwu + r * JH_U + tig;
            const unsigned* ar1 = ar0 + 8 * JH_U;
            #pragma unroll
            for (int kt = 0; kt < 5; kt++) {
                unsigned a0 = ar0[kt * 8];
                unsigned a1f = ar1[kt * 8];
                unsigned a2 = ar0[kt * 8 + 4];
                unsigned a3 = ar1[kt * 8 + 4];
                const float4* bp = (const float4*)ws + kt * 400 + lane;
                #pragma unroll
                for (int p = 0; p < 12; p++) {
                    float4 b = bp[p * 32];
                    mma_f16(acc[2*p],   a0, a1f, a2, a3,
                            __float_as_uint(b.x), __float_as_uint(b.y));
                    mma_f16(acc[2*p+1], a0, a1f, a2, a3,
                            __float_as_uint(b.z), __float_as_uint(b.w));
                }
                const uint2 bsg = *(const uint2*)(ws + kt * 1600 + 1536 + lane * 2);
                mma_f16(acc[24], a0, a1f, a2, a3, bsg.x, bsg.y);
            }
        }

        // ======== bias + PReLU + LN1 stats =============================
        float m0, m1, rs0, rs1;
        {
            float s0 = 0.f, q0 = 0.f, s1 = 0.f, q1 = 0.f;
            #pragma unroll
            for (int nt = 0; nt < 25; nt++) {
                int f0 = nt * 8 + 2 * tig;
                float2 bb = *(const float2*)&b1s[f0];
                float v;
                v = acc[nt][0] + bb.x; v = (v >= 0.f) ? v : a1v * v; if (f0     >= DHID) v = 0.f;
                acc[nt][0] = v; s0 += v; q0 += v * v;
                v = acc[nt][1] + bb.y; v = (v >= 0.f) ? v : a1v * v; if (f0 + 1 >= DHID) v = 0.f;
                acc[nt][1] = v; s0 += v; q0 += v * v;
                v = acc[nt][2] + bb.x; v = (v >= 0.f) ? v : a1v * v; if (f0     >= DHID) v = 0.f;
                acc[nt][2] = v; s1 += v; q1 += v * v;
                v = acc[nt][3] + bb.y; v = (v >= 0.f) ? v : a1v * v; if (f0 + 1 >= DHID) v = 0.f;
                acc[nt][3] = v; s1 += v; q1 += v * v;
            }
            s0 += __shfl_xor_sync(0xffffffffu, s0, 1); q0 += __shfl_xor_sync(0xffffffffu, q0, 1);
            s1 += __shfl_xor_sync(0xffffffffu, s1, 1); q1 += __shfl_xor_sync(0xffffffffu, q1, 1);
            s0 += __shfl_xor_sync(0xffffffffu, s0, 2); q0 += __shfl_xor_sync(0xffffffffu, q0, 2);
            s1 += __shfl_xor_sync(0xffffffffu, s1, 2); q1 += __shfl_xor_sync(0xffffffffu, q1, 2);
            m0 = s0 * (1.f / DHID); m1 = s1 * (1.f / DHID);
            rs0 = rsqrtf(q0 * (1.f / DHID) - m0 * m0 + 1e-5f);
            rs1 = rsqrtf(q1 * (1.f / DHID) - m1 * m1 + 1e-5f);
        }

        // ======== LN1 apply + pack to A-fragments (C==A layout) ========
        unsigned ah[25][2];
        #pragma unroll
        for (int nt = 0; nt < 25; nt++) {
            int f0 = nt * 8 + 2 * tig;
            float2 aa = albe1[f0];
            float2 ab = albe1[f0 + 1];
            ah[nt][0] = pack_h2((acc[nt][0] - m0) * rs0 * aa.x + aa.y,
                                (acc[nt][1] - m0) * rs0 * ab.x + ab.y);
            ah[nt][1] = pack_h2((acc[nt][2] - m1) * rs1 * aa.x + aa.y,
                                (acc[nt][3] - m1) * rs1 * ab.x + ab.y);
        }

        // ================= GEMM2: C[16tok x 80], 13 k-tiles ============
        float acc2[10][4];
        #pragma unroll
        for (int nt = 0; nt < 10; nt++)
            #pragma unroll
            for (int i = 0; i < 4; i++) acc2[nt][i] = 0.f;

        {
            #pragma unroll
            for (int kt = 0; kt < 13; kt++) {
                unsigned a0, a1f, a2, a3;
                if (kt < 12) {
                    a0 = ah[2*kt][0];   a1f = ah[2*kt][1];
                    a2 = ah[2*kt+1][0]; a3  = ah[2*kt+1][1];
                } else {
                    a0 = ah[24][0]; a1f = ah[24][1]; a2 = 0u; a3 = 0u;
                }
                const float4* bp = (const float4*)w2s + kt * 160 + lane;
                #pragma unroll
                for (int p = 0; p < 5; p++) {
                    float4 b = bp[p * 32];
                    mma_f16(acc2[2*p],   a0, a1f, a2, a3,
                            __float_as_uint(b.x), __float_as_uint(b.y));
                    mma_f16(acc2[2*p+1], a0, a1f, a2, a3,
                            __float_as_uint(b.z), __float_as_uint(b.w));
                }
            }
        }

        // ======== bias + PReLU + LN2 stats =============================
        float m0b, m1b, r0b, r1b;
        {
            float s0 = 0.f, q0 = 0.f, s1 = 0.f, q1 = 0.f;
            #pragma unroll
            for (int nt = 0; nt < 10; nt++) {
                int f0 = nt * 8 + 2 * tig;
                float2 bb = *(const float2*)&b2s[f0];
                float v;
                v = acc2[nt][0] + bb.x; v = (v >= 0.f) ? v : a2v * v; if (f0     >= DIN) v = 0.f;
                acc2[nt][0] = v; s0 += v; q0 += v * v;
                v = acc2[nt][1] + bb.y; v = (v >= 0.f) ? v : a2v * v; if (f0 + 1 >= DIN) v = 0.f;
                acc2[nt][1] = v; s0 += v; q0 += v * v;
                v = acc2[nt][2] + bb.x; v = (v >= 0.f) ? v : a2v * v; if (f0     >= DIN) v = 0.f;
                acc2[nt][2] = v; s1 += v; q1 += v * v;
                v = acc2[nt][3] + bb.y; v = (v >= 0.f) ? v : a2v * v; if (f0 + 1 >= DIN) v = 0.f;
                acc2[nt][3] = v; s1 += v; q1 += v * v;
            }
            s0 += __shfl_xor_sync(0xffffffffu, s0, 1); q0 += __shfl_xor_sync(0xffffffffu, q0, 1);
            s1 += __shfl_xor_sync(0xffffffffu, s1, 1); q1 += __shfl_xor_sync(0xffffffffu, q1, 1);
            s0 += __shfl_xor_sync(0xffffffffu, s0, 2); q0 += __shfl_xor_sync(0xffffffffu, q0, 2);
            s1 += __shfl_xor_sync(0xffffffffu, s1, 2); q1 += __shfl_xor_sync(0xffffffffu, q1, 2);
            m0b = s0 * (1.f / DIN); m1b = s1 * (1.f / DIN);
            r0b = rsqrtf(q0 * (1.f / DIN) - m0b * m0b + 1e-5f);
            r1b = rsqrtf(q1 * (1.f / DIN) - m1b * m1b + 1e-5f);
        }

        // ======== staged epilogue: two row-half passes through smem ====
        const size_t yofs = (size_t)ntok * KPS;
        #pragma unroll
        for (int half = 0; half < 2; half++) {
            const float mb = half ? m1b : m0b;
            const float rb = half ? r1b : r0b;
            __syncwarp();
            // normalize + scatter into slab: one STS.64 per nt, padded stride
            #pragma unroll
            for (int nt = 0; nt < 10; nt++) {
                int f0 = nt * 8 + 2 * tig;
                float2 aa = albe2[f0];
                float2 ab = albe2[f0 + 1];
                float c0 = half ? acc2[nt][2] : acc2[nt][0];
                float c1 = half ? acc2[nt][3] : acc2[nt][1];
                float2 o2;
                o2.x = (c0 - mb) * rb * aa.x + aa.y;
                o2.y = (c1 - mb) * rb * ab.x + ab.y;
                *(float2*)&oslw[r * OSL_S + f0] = o2;
            }
            __syncwarp();
            // coalesced drain: 8 tokens x 78 features, residual from gmem,
            // streaming stores (out is never re-read)
            const int t0 = gt0w + half * 8;
            const float* xs = x   + (size_t)t0 * KPS;
            const float* ys = y   + (size_t)t0 * KPS;
            float*       ox = out + (size_t)t0 * KPS;
            float*       oy = out + yofs + (size_t)t0 * KPS;
            if (t0 + 8 <= ntok) {
                #pragma unroll
                for (int i = 0; i < 20; i++) {
                    int idx = lane + 32 * i;
                    if (idx < 624) {
                        int t = idx / DIN, f = idx - t * DIN;
                        float v = oslw[t * OSL_S + f];
                        if (f < KPS) __stcs(&ox[t * KPS + f],       v + xs[t * KPS + f]);
                        else         __stcs(&oy[t * KPS + f - KPS], v + ys[t * KPS + f - KPS]);
                    }
                }
            } else {
                #pragma unroll
                for (int i = 0; i < 20; i++) {
                    int idx = lane + 32 * i;
                    if (idx < 624) {
                        int t = idx / DIN, f = idx - t * DIN;
                        if (t0 + t < ntok) {
                            float v = oslw[t * OSL_S + f];
                            if (f < KPS) __stcs(&ox[t * KPS + f],       v + xs[t * KPS + f]);
                            else         __stcs(&oy[t * KPS + f - KPS], v + ys[t * KPS + f - KPS]);
                        }
                    }
                }
            }
        }
    }
}

extern "C" void kernel_launch(void* const* d_in, const int* in_sizes, int n_in,
                              void* d_out, int out_size) {
    const float* x      = (const float*)d_in[0];
    const float* y      = (const float*)d_in[1];
    const float* W1     = (const float*)d_in[2];
    const float* b1     = (const float*)d_in[3];
    const float* W2     = (const float*)d_in[4];
    const float* b2     = (const float*)d_in[5];
    const float* a1     = (const float*)d_in[6];
    const float* a2     = (const float*)d_in[7];
    const float* alpha1 = (const float*)d_in[8];
    const float* beta1  = (const float*)d_in[9];
    const float* alpha2 = (const float*)d_in[10];
    const float* beta2  = (const float*)d_in[11];
    float* out = (float*)d_out;

    int ntok   = in_sizes[0] / KPS;
    int ntiles = (ntok + TB - 1) / TB;

    int dev = 0, nsm = 148;
    cudaGetDevice(&dev);
    cudaDeviceGetAttribute(&nsm, cudaDevAttrMultiProcessorCount, dev);
    int grid = 2 * nsm;
    if (grid > ntiles) grid = ntiles;

    size_t smem = SMEM_WORDS * sizeof(unsigned);

    prep_weights_kernel<<<64, 256>>>(W1, W2);

    cudaFuncSetAttribute(spatialctx_tc_kernel,
                         cudaFuncAttributeMaxDynamicSharedMemorySize, (int)smem);
    cudaFuncSetAttribute(spatialctx_tc_kernel,
                         cudaFuncAttributePreferredSharedMemoryCarveout, 100);
    spatialctx_tc_kernel<<<grid, NT, smem>>>(
        x, y, b1, b2, a1, a2, alpha1, beta1, alpha2, beta2, out, ntok, ntiles);
}

// round 14
// speedup vs baseline: 1.1328x; 1.1328x over previous
#include <cuda_runtime.h>
#include <cuda_fp16.h>

#define KPS   39
#define DIN   78
#define DHID  195
#define TB    128      // tokens per tile
#define NT    256      // 8 warps, 16 tokens each

// uint offsets into dynamic smem
#define OFS_WS    0        // w1h frags 8000 u
#define OFS_W2    8000     // w2h frags 8320 u
#define OFS_JH    16320    // uint[128][44]  (= half[128][88]) : 5632 u
#define OFS_B1    21952    // 200 f
#define OFS_ALBE1 22152    // 400 f
#define OFS_B2    22552    // 80 f
#define OFS_ALBE2 22632    // 160 f
#define OFS_OSL   22792    // out slab: 8 warps x 8 rows x 84 f = 5376 f
#define SMEM_WORDS 28168   // 112672 bytes -> 2 CTAs/SM

#define JH_U  44           // uint stride per token row (88 halves)
#define OSL_S 84           // slab row stride (floats)

// fp16 weight fragment scratch (prepped once per launch), uint = fp16x2
__device__ unsigned g_w1h[8000];   // per kt(5): 12 nt-pairs [p][lane][4] + nt=24 [lane][2]
__device__ unsigned g_w2h[8320];   // per kt(13): 5 nt-pairs [p][lane][4]

__device__ __forceinline__ void mma_f16(float c[4],
                                        unsigned a0, unsigned a1, unsigned a2, unsigned a3,
                                        unsigned b0, unsigned b1) {
    asm volatile(
        "mma.sync.aligned.m16n8k16.row.col.f32.f16.f16.f32 "
        "{%0,%1,%2,%3}, {%4,%5,%6,%7}, {%8,%9}, {%0,%1,%2,%3};"
        : "+f"(c[0]), "+f"(c[1]), "+f"(c[2]), "+f"(c[3])
        : "r"(a0), "r"(a1), "r"(a2), "r"(a3), "r"(b0), "r"(b1));
}

__device__ __forceinline__ unsigned pack_h2(float lo, float hi) {
    __half2 h = __floats2half2_rn(lo, hi);
    return *(unsigned*)&h;
}

// ---------- prep: fp16-pack weights into mma fragment layout ----------
__global__ void prep_weights_kernel(const float* __restrict__ W1,
                                    const float* __restrict__ W2)
{
    int o = blockIdx.x * 256 + threadIdx.x;       // 0..16319
    if (o < 8000) {
        int kt  = o / 1600;
        int rem = o - kt * 1600;
        int n, kbase;
        if (rem < 1536) {
            int p    = rem >> 7;
            int q    = rem & 127;
            int lane = q >> 2, fi = q & 3;
            int gid = lane >> 2, tig = lane & 3;
            int nt  = 2 * p + (fi >> 1);
            n = nt * 8 + gid;
            kbase = kt * 16 + 2 * tig + 8 * (fi & 1);
        } else {
            int q    = rem - 1536;
            int lane = q >> 1, reg = q & 1;
            int gid = lane >> 2, tig = lane & 3;
            n = 192 + gid;
            kbase = kt * 16 + 2 * tig + 8 * reg;
        }
        float lo = (n < DHID && kbase     < DIN) ? W1[n * DIN + kbase]     : 0.f;
        float hi = (n < DHID && kbase + 1 < DIN) ? W1[n * DIN + kbase + 1] : 0.f;
        g_w1h[o] = pack_h2(lo, hi);
    } else if (o < 16320) {
        int o2  = o - 8000;
        int kt  = o2 / 640;
        int rem = o2 - kt * 640;
        int p    = rem >> 7;
        int q    = rem & 127;
        int lane = q >> 2, fi = q & 3;
        int gid = lane >> 2, tig = lane & 3;
        int nt  = 2 * p + (fi >> 1);
        int n = nt * 8 + gid;
        int kbase = kt * 16 + 2 * tig + 8 * (fi & 1);
        float lo = (n < DIN && kbase     < DHID) ? W2[n * DHID + kbase]     : 0.f;
        float hi = (n < DIN && kbase + 1 < DHID) ? W2[n * DHID + kbase + 1] : 0.f;
        g_w2h[o2] = pack_h2(lo, hi);
    }
}

// --------------------------------- main (persistent) ---------------------------------
__global__ __launch_bounds__(NT, 2)
void spatialctx_tc_kernel(
    const float* __restrict__ x, const float* __restrict__ y,
    const float* __restrict__ b1, const float* __restrict__ b2,
    const float* __restrict__ a1, const float* __restrict__ a2,
    const float* __restrict__ alpha1, const float* __restrict__ beta1,
    const float* __restrict__ alpha2, const float* __restrict__ beta2,
    float* __restrict__ out, int ntok, int ntiles)
{
    extern __shared__ unsigned smu[];
    unsigned* ws    = smu + OFS_WS;
    unsigned* w2s   = smu + OFS_W2;
    unsigned* jh    = smu + OFS_JH;
    float*    b1s   = (float*)(smu + OFS_B1);
    float2*   albe1 = (float2*)(smu + OFS_ALBE1);
    float*    b2s   = (float*)(smu + OFS_B2);
    float2*   albe2 = (float2*)(smu + OFS_ALBE2);
    float*    osl   = (float*)(smu + OFS_OSL);

    const int tid = threadIdx.x;

    // ---- prologue: stage both weight-fragment sets (once) ----
    {
        const float4* s1 = (const float4*)g_w1h;
        float4* d1 = (float4*)ws;
        #pragma unroll
        for (int i = 0; i < 8; i++) {
            int o = tid + i * NT;
            if (o < 2000) d1[o] = s1[o];
        }
        const float4* s2 = (const float4*)g_w2h;
        float4* d2 = (float4*)w2s;
        #pragma unroll
        for (int i = 0; i < 9; i++) {
            int o = tid + i * NT;
            if (o < 2080) d2[o] = s2[o];
        }
    }
    if (tid < 200) {
        b1s[tid] = (tid < DHID) ? b1[tid] : 0.f;
        albe1[tid] = make_float2((tid < DHID) ? alpha1[tid] : 0.f,
                                 (tid < DHID) ? beta1[tid]  : 0.f);
    }
    if (tid < 80) {
        b2s[tid] = (tid < DIN) ? b2[tid] : 0.f;
        albe2[tid] = make_float2((tid < DIN) ? alpha2[tid] : 0.f,
                                 (tid < DIN) ? beta2[tid]  : 0.f);
    }
    if (tid < 128) {       // zero the jh pad columns (halves 78..87) once
        #pragma unroll
        for (int c = 39; c < 44; c++) jh[tid * JH_U + c] = 0u;
    }
    const float a1v = a1[0];
    const float a2v = a2[0];
    __syncthreads();       // the only block-wide barrier

    const int warp   = tid >> 5;
    const int lane   = tid & 31;
    const int r      = lane >> 2;
    const int tig    = lane & 3;
    const int tokrow = warp * 16;

    unsigned* jwu  = jh + tokrow * JH_U;            // warp-private rows
    __half*   jwh  = (__half*)jwu;
    float*    oslw = osl + warp * (8 * OSL_S);      // warp-private 8x84 slab

    for (int tile = blockIdx.x; tile < ntiles; tile += gridDim.x) {
        const int tbase = tile * TB;
        const int gt0w  = tbase + tokrow;          // warp's first token

        // ---- stage warp's 16 token rows: coalesced x,y slab reads ----
        __syncwarp();
        {
            const float* xs = x + (size_t)gt0w * KPS;
            const float* ys = y + (size_t)gt0w * KPS;
            if (gt0w + 16 <= ntok) {
                #pragma unroll
                for (int i = 0; i < 20; i++) {
                    int idx = lane + 32 * i;
                    if (idx < 624) {
                        int t = idx / KPS, d = idx - t * KPS;
                        jwh[t * 88 + d]       = __float2half(xs[idx]);
                        jwh[t * 88 + d + KPS] = __float2half(ys[idx]);
                    }
                }
            } else {
                #pragma unroll
                for (int i = 0; i < 20; i++) {
                    int idx = lane + 32 * i;
                    if (idx < 624) {
                        int t = idx / KPS, d = idx - t * KPS;
                        bool ok = (gt0w + t) < ntok;
                        jwh[t * 88 + d]       = __float2half(ok ? xs[idx] : 0.f);
                        jwh[t * 88 + d + KPS] = __float2half(ok ? ys[idx] : 0.f);
                    }
                }
            }
        }
        // ---- L2 prefetch of next tile's slabs (coalesced 128B steps) ----
        {
            int ntile = tile + gridDim.x;
            if (ntile < ntiles && lane < 20) {
                const float* px = x + (size_t)(ntile * TB + tokrow) * KPS + lane * 32;
                const float* py = y + (size_t)(ntile * TB + tokrow) * KPS + lane * 32;
                asm volatile("prefetch.global.L2 [%0];" :: "l"(px));
                asm volatile("prefetch.global.L2 [%0];" :: "l"(py));
            }
        }
        __syncwarp();

        // ================= GEMM1: C[16tok x 200], 5 k-tiles ============
        float acc[25][4];
        #pragma unroll
        for (int nt = 0; nt < 25; nt++)
            #pragma unroll
            for (int i = 0; i < 4; i++) acc[nt][i] = 0.f;

        {
            const unsigned* ar0 = jwu + r * JH_U + tig;
            const unsigned* ar1 = ar0 + 8 * JH_U;
            #pragma unroll
            for (int kt = 0; kt < 5; kt++) {
                unsigned a0 = ar0[kt * 8];
                unsigned a1f = ar1[kt * 8];
                unsigned a2 = ar0[kt * 8 + 4];
                unsigned a3 = ar1[kt * 8 + 4];
                const float4* bp = (const float4*)ws + kt * 400 + lane;
                #pragma unroll
                for (int p = 0; p < 12; p++) {
                    float4 b = bp[p * 32];
                    mma_f16(acc[2*p],   a0, a1f, a2, a3,
                            __float_as_uint(b.x), __float_as_uint(b.y));
                    mma_f16(acc[2*p+1], a0, a1f, a2, a3,
                            __float_as_uint(b.z), __float_as_uint(b.w));
                }
                const uint2 bsg = *(const uint2*)(ws + kt * 1600 + 1536 + lane * 2);
                mma_f16(acc[24], a0, a1f, a2, a3, bsg.x, bsg.y);
            }
        }

        // ======== bias + PReLU + LN1 stats =============================
        float m0, m1, rs0, rs1;
        {
            float s0 = 0.f, q0 = 0.f, s1 = 0.f, q1 = 0.f;
            #pragma unroll
            for (int nt = 0; nt < 25; nt++) {
                int f0 = nt * 8 + 2 * tig;
                float2 bb = *(const float2*)&b1s[f0];
                float v;
                v = acc[nt][0] + bb.x; v = (v >= 0.f) ? v : a1v * v; if (f0     >= DHID) v = 0.f;
                acc[nt][0] = v; s0 += v; q0 += v * v;
                v = acc[nt][1] + bb.y; v = (v >= 0.f) ? v : a1v * v; if (f0 + 1 >= DHID) v = 0.f;
                acc[nt][1] = v; s0 += v; q0 += v * v;
                v = acc[nt][2] + bb.x; v = (v >= 0.f) ? v : a1v * v; if (f0     >= DHID) v = 0.f;
                acc[nt][2] = v; s1 += v; q1 += v * v;
                v = acc[nt][3] + bb.y; v = (v >= 0.f) ? v : a1v * v; if (f0 + 1 >= DHID) v = 0.f;
                acc[nt][3] = v; s1 += v; q1 += v * v;
            }
            s0 += __shfl_xor_sync(0xffffffffu, s0, 1); q0 += __shfl_xor_sync(0xffffffffu, q0, 1);
            s1 += __shfl_xor_sync(0xffffffffu, s1, 1); q1 += __shfl_xor_sync(0xffffffffu, q1, 1);
            s0 += __shfl_xor_sync(0xffffffffu, s0, 2); q0 += __shfl_xor_sync(0xffffffffu, q0, 2);
            s1 += __shfl_xor_sync(0xffffffffu, s1, 2); q1 += __shfl_xor_sync(0xffffffffu, q1, 2);
            m0 = s0 * (1.f / DHID); m1 = s1 * (1.f / DHID);
            rs0 = rsqrtf(q0 * (1.f / DHID) - m0 * m0 + 1e-5f);
            rs1 = rsqrtf(q1 * (1.f / DHID) - m1 * m1 + 1e-5f);
        }

        // ======== LN1 apply + pack to A-fragments (C==A layout) ========
        unsigned ah[25][2];
        #pragma unroll
        for (int nt = 0; nt < 25; nt++) {
            int f0 = nt * 8 + 2 * tig;
            float2 aa = albe1[f0];
            float2 ab = albe1[f0 + 1];
            ah[nt][0] = pack_h2((acc[nt][0] - m0) * rs0 * aa.x + aa.y,
                                (acc[nt][1] - m0) * rs0 * ab.x + ab.y);
            ah[nt][1] = pack_h2((acc[nt][2] - m1) * rs1 * aa.x + aa.y,
                                (acc[nt][3] - m1) * rs1 * ab.x + ab.y);
        }

        // ================= GEMM2: C[16tok x 80], 13 k-tiles ============
        float acc2[10][4];
        #pragma unroll
        for (int nt = 0; nt < 10; nt++)
            #pragma unroll
            for (int i = 0; i < 4; i++) acc2[nt][i] = 0.f;

        {
            #pragma unroll
            for (int kt = 0; kt < 13; kt++) {
                unsigned a0, a1f, a2, a3;
                if (kt < 12) {
                    a0 = ah[2*kt][0];   a1f = ah[2*kt][1];
                    a2 = ah[2*kt+1][0]; a3  = ah[2*kt+1][1];
                } else {
                    a0 = ah[24][0]; a1f = ah[24][1]; a2 = 0u; a3 = 0u;
                }
                const float4* bp = (const float4*)w2s + kt * 160 + lane;
                #pragma unroll
                for (int p = 0; p < 5; p++) {
                    float4 b = bp[p * 32];
                    mma_f16(acc2[2*p],   a0, a1f, a2, a3,
                            __float_as_uint(b.x), __float_as_uint(b.y));
                    mma_f16(acc2[2*p+1], a0, a1f, a2, a3,
                            __float_as_uint(b.z), __float_as_uint(b.w));
                }
            }
        }

        // ======== bias + PReLU + LN2 stats =============================
        float m0b, m1b, r0b, r1b;
        {
            float s0 = 0.f, q0 = 0.f, s1 = 0.f, q1 = 0.f;
            #pragma unroll
            for (int nt = 0; nt < 10; nt++) {
                int f0 = nt * 8 + 2 * tig;
                float2 bb = *(const float2*)&b2s[f0];
                float v;
                v = acc2[nt][0] + bb.x; v = (v >= 0.f) ? v : a2v * v; if (f0     >= DIN) v = 0.f;
                acc2[nt][0] = v; s0 += v; q0 += v * v;
                v = acc2[nt][1] + bb.y; v = (v >= 0.f) ? v : a2v * v; if (f0 + 1 >= DIN) v = 0.f;
                acc2[nt][1] = v; s0 += v; q0 += v * v;
                v = acc2[nt][2] + bb.x; v = (v >= 0.f) ? v : a2v * v; if (f0     >= DIN) v = 0.f;
                acc2[nt][2] = v; s1 += v; q1 += v * v;
                v = acc2[nt][3] + bb.y; v = (v >= 0.f) ? v : a2v * v; if (f0 + 1 >= DIN) v = 0.f;
                acc2[nt][3] = v; s1 += v; q1 += v * v;
            }
            s0 += __shfl_xor_sync(0xffffffffu, s0, 1); q0 += __shfl_xor_sync(0xffffffffu, q0, 1);
            s1 += __shfl_xor_sync(0xffffffffu, s1, 1); q1 += __shfl_xor_sync(0xffffffffu, q1, 1);
            s0 += __shfl_xor_sync(0xffffffffu, s0, 2); q0 += __shfl_xor_sync(0xffffffffu, q0, 2);
            s1 += __shfl_xor_sync(0xffffffffu, s1, 2); q1 += __shfl_xor_sync(0xffffffffu, q1, 2);
            m0b = s0 * (1.f / DIN); m1b = s1 * (1.f / DIN);
            r0b = rsqrtf(q0 * (1.f / DIN) - m0b * m0b + 1e-5f);
            r1b = rsqrtf(q1 * (1.f / DIN) - m1b * m1b + 1e-5f);
        }

        // ======== staged epilogue: two row-half passes through smem ====
        const size_t yofs = (size_t)ntok * KPS;
        #pragma unroll
        for (int half = 0; half < 2; half++) {
            const float mb = half ? m1b : m0b;
            const float rb = half ? r1b : r0b;
            __syncwarp();
            // normalize + scatter into slab: one STS.64 per nt, padded stride
            #pragma unroll
            for (int nt = 0; nt < 10; nt++) {
                int f0 = nt * 8 + 2 * tig;
                float2 aa = albe2[f0];
                float2 ab = albe2[f0 + 1];
                float c0 = half ? acc2[nt][2] : acc2[nt][0];
                float c1 = half ? acc2[nt][3] : acc2[nt][1];
                float2 o2;
                o2.x = (c0 - mb) * rb * aa.x + aa.y;
                o2.y = (c1 - mb) * rb * ab.x + ab.y;
                *(float2*)&oslw[r * OSL_S + f0] = o2;
            }
            __syncwarp();
            // coalesced drain: 8 tokens x 78 features, residual from gmem,
            // streaming stores (out is never re-read)
            const int t0 = gt0w + half * 8;
            const float* xs = x   + (size_t)t0 * KPS;
            const float* ys = y   + (size_t)t0 * KPS;
            float*       ox = out + (size_t)t0 * KPS;
            float*       oy = out + yofs + (size_t)t0 * KPS;
            if (t0 + 8 <= ntok) {
                #pragma unroll
                for (int i = 0; i < 20; i++) {
                    int idx = lane + 32 * i;
                    if (idx < 624) {
                        int t = idx / DIN, f = idx - t * DIN;
                        float v = oslw[t * OSL_S + f];
                        if (f < KPS) __stcs(&ox[t * KPS + f],       v + xs[t * KPS + f]);
                        else         __stcs(&oy[t * KPS + f - KPS], v + ys[t * KPS + f - KPS]);
                    }
                }
            } else {
                #pragma unroll
                for (int i = 0; i < 20; i++) {
                    int idx = lane + 32 * i;
                    if (idx < 624) {
                        int t = idx / DIN, f = idx - t * DIN;
                        if (t0 + t < ntok) {
                            float v = oslw[t * OSL_S + f];
                            if (f < KPS) __stcs(&ox[t * KPS + f],       v + xs[t * KPS + f]);
                            else         __stcs(&oy[t * KPS + f - KPS], v + ys[t * KPS + f - KPS]);
                        }
                    }
                }
            }
        }
    }
}

extern "C" void kernel_launch(void* const* d_in, const int* in_sizes, int n_in,
                              void* d_out, int out_size) {
    const float* x      = (const float*)d_in[0];
    const float* y      = (const float*)d_in[1];
    const float* W1     = (const float*)d_in[2];
    const float* b1     = (const float*)d_in[3];
    const float* W2     = (const float*)d_in[4];
    const float* b2     = (const float*)d_in[5];
    const float* a1     = (const float*)d_in[6];
    const float* a2     = (const float*)d_in[7];
    const float* alpha1 = (const float*)d_in[8];
    const float* beta1  = (const float*)d_in[9];
    const float* alpha2 = (const float*)d_in[10];
    const float* beta2  = (const float*)d_in[11];
    float* out = (float*)d_out;

    int ntok   = in_sizes[0] / KPS;
    int ntiles = (ntok + TB - 1) / TB;

    int dev = 0, nsm = 148;
    cudaGetDevice(&dev);
    cudaDeviceGetAttribute(&nsm, cudaDevAttrMultiProcessorCount, dev);
    int grid = 2 * nsm;
    if (grid > ntiles) grid = ntiles;

    size_t smem = SMEM_WORDS * sizeof(unsigned);

    prep_weights_kernel<<<64, 256>>>(W1, W2);

    cudaFuncSetAttribute(spatialctx_tc_kernel,
                         cudaFuncAttributeMaxDynamicSharedMemorySize, (int)smem);
    cudaFuncSetAttribute(spatialctx_tc_kernel,
                         cudaFuncAttributePreferredSharedMemoryCarveout, 100);
    spatialctx_tc_kernel<<<grid, NT, smem>>>(
        x, y, b1, b2, a1, a2, alpha1, beta1, alpha2, beta2, out, ntok, ntiles);
}

// round 15
// speedup vs baseline: 1.1374x; 1.0040x over previous
#include <cuda_runtime.h>
#include <cuda_fp16.h>

#define KPS   39
#define DIN   78
#define DHID  195
#define TB    128      // tokens per tile
#define NT    256      // 8 warps, 16 tokens each

// uint offsets into dynamic smem
#define OFS_WS    0        // w1h frags 8000 u
#define OFS_W2    8000     // w2h frags 8320 u
#define OFS_JH    16320    // uint[128][44]  (= half[128][88]) : 5632 u
#define OFS_B1    21952    // 200 f
#define OFS_ALBE1 22152    // 400 f
#define OFS_B2    22552    // 80 f
#define OFS_ALBE2 22632    // 160 f
#define OFS_OSL   22792    // out slab: 8 warps x 8 rows x 84 f = 5376 f
#define SMEM_WORDS 28168   // 112672 bytes -> 2 CTAs/SM

#define JH_U  44           // uint stride per token row (88 halves)
#define OSL_S 84           // slab row stride (floats)

// fp16 weight fragment scratch (prepped once per launch), uint = fp16x2
__device__ unsigned g_w1h[8000];   // per kt(5): 12 nt-pairs [p][lane][4] + nt=24 [lane][2]
__device__ unsigned g_w2h[8320];   // per kt(13): 5 nt-pairs [p][lane][4]

__device__ __forceinline__ void mma_f16(float c[4],
                                        unsigned a0, unsigned a1, unsigned a2, unsigned a3,
                                        unsigned b0, unsigned b1) {
    asm volatile(
        "mma.sync.aligned.m16n8k16.row.col.f32.f16.f16.f32 "
        "{%0,%1,%2,%3}, {%4,%5,%6,%7}, {%8,%9}, {%0,%1,%2,%3};"
        : "+f"(c[0]), "+f"(c[1]), "+f"(c[2]), "+f"(c[3])
        : "r"(a0), "r"(a1), "r"(a2), "r"(a3), "r"(b0), "r"(b1));
}

__device__ __forceinline__ unsigned pack_h2(float lo, float hi) {
    __half2 h = __floats2half2_rn(lo, hi);
    return *(unsigned*)&h;
}

// ---------- prep: fp16-pack weights into mma fragment layout ----------
__global__ void prep_weights_kernel(const float* __restrict__ W1,
                                    const float* __restrict__ W2)
{
    int o = blockIdx.x * 256 + threadIdx.x;       // 0..16319
    if (o < 8000) {
        int kt  = o / 1600;
        int rem = o - kt * 1600;
        int n, kbase;
        if (rem < 1536) {
            int p    = rem >> 7;
            int q    = rem & 127;
            int lane = q >> 2, fi = q & 3;
            int gid = lane >> 2, tig = lane & 3;
            int nt  = 2 * p + (fi >> 1);
            n = nt * 8 + gid;
            kbase = kt * 16 + 2 * tig + 8 * (fi & 1);
        } else {
            int q    = rem - 1536;
            int lane = q >> 1, reg = q & 1;
            int gid = lane >> 2, tig = lane & 3;
            n = 192 + gid;
            kbase = kt * 16 + 2 * tig + 8 * reg;
        }
        float lo = (n < DHID && kbase     < DIN) ? W1[n * DIN + kbase]     : 0.f;
        float hi = (n < DHID && kbase + 1 < DIN) ? W1[n * DIN + kbase + 1] : 0.f;
        g_w1h[o] = pack_h2(lo, hi);
    } else if (o < 16320) {
        int o2  = o - 8000;
        int kt  = o2 / 640;
        int rem = o2 - kt * 640;
        int p    = rem >> 7;
        int q    = rem & 127;
        int lane = q >> 2, fi = q & 3;
        int gid = lane >> 2, tig = lane & 3;
        int nt  = 2 * p + (fi >> 1);
        int n = nt * 8 + gid;
        int kbase = kt * 16 + 2 * tig + 8 * (fi & 1);
        float lo = (n < DIN && kbase     < DHID) ? W2[n * DHID + kbase]     : 0.f;
        float hi = (n < DIN && kbase + 1 < DHID) ? W2[n * DHID + kbase + 1] : 0.f;
        g_w2h[o2] = pack_h2(lo, hi);
    }
}

// --------------------------------- main (persistent) ---------------------------------
__global__ __launch_bounds__(NT, 2)
void spatialctx_tc_kernel(
    const float* __restrict__ x, const float* __restrict__ y,
    const float* __restrict__ b1, const float* __restrict__ b2,
    const float* __restrict__ a1, const float* __restrict__ a2,
    const float* __restrict__ alpha1, const float* __restrict__ beta1,
    const float* __restrict__ alpha2, const float* __restrict__ beta2,
    float* __restrict__ out, int ntok, int ntiles)
{
    extern __shared__ unsigned smu[];
    unsigned* ws    = smu + OFS_WS;
    unsigned* w2s   = smu + OFS_W2;
    unsigned* jh    = smu + OFS_JH;
    float*    b1s   = (float*)(smu + OFS_B1);
    float2*   albe1 = (float2*)(smu + OFS_ALBE1);
    float*    b2s   = (float*)(smu + OFS_B2);
    float2*   albe2 = (float2*)(smu + OFS_ALBE2);
    float*    osl   = (float*)(smu + OFS_OSL);

    const int tid = threadIdx.x;

    // ---- prologue: stage both weight-fragment sets (once) ----
    {
        const float4* s1 = (const float4*)g_w1h;
        float4* d1 = (float4*)ws;
        #pragma unroll
        for (int i = 0; i < 8; i++) {
            int o = tid + i * NT;
            if (o < 2000) d1[o] = s1[o];
        }
        const float4* s2 = (const float4*)g_w2h;
        float4* d2 = (float4*)w2s;
        #pragma unroll
        for (int i = 0; i < 9; i++) {
            int o = tid + i * NT;
            if (o < 2080) d2[o] = s2[o];
        }
    }
    if (tid < 200) {
        b1s[tid] = (tid < DHID) ? b1[tid] : 0.f;
        albe1[tid] = make_float2((tid < DHID) ? alpha1[tid] : 0.f,
                                 (tid < DHID) ? beta1[tid]  : 0.f);
    }
    if (tid < 80) {
        b2s[tid] = (tid < DIN) ? b2[tid] : 0.f;
        albe2[tid] = make_float2((tid < DIN) ? alpha2[tid] : 0.f,
                                 (tid < DIN) ? beta2[tid]  : 0.f);
    }
    if (tid < 128) {       // zero the jh pad columns (halves 78..87) once
        #pragma unroll
        for (int c = 39; c < 44; c++) jh[tid * JH_U + c] = 0u;
    }
    const float a1v = a1[0];
    const float a2v = a2[0];
    __syncthreads();       // the only block-wide barrier

    const int warp   = tid >> 5;
    const int lane   = tid & 31;
    const int r      = lane >> 2;
    const int tig    = lane & 3;
    const int tokrow = warp * 16;

    unsigned* jwu  = jh + tokrow * JH_U;            // warp-private rows
    __half*   jwh  = (__half*)jwu;
    float*    oslw = osl + warp * (8 * OSL_S);      // warp-private 8x84 slab

    for (int tile = blockIdx.x; tile < ntiles; tile += gridDim.x) {
        const int tbase = tile * TB;
        const int gt0w  = tbase + tokrow;          // warp's first token

        // ---- stage warp's 16 token rows: x,y slabs are contiguous ----
        __syncwarp();
        {
            const float* xs = x + (size_t)gt0w * KPS;
            const float* ys = y + (size_t)gt0w * KPS;
            if (gt0w + 16 <= ntok) {
                #pragma unroll
                for (int i = 0; i < 20; i++) {
                    int idx = lane + 32 * i;
                    if (idx < 624) {
                        int t = idx / KPS, d = idx - t * KPS;
                        jwh[t * 88 + d]       = __float2half(xs[idx]);
                        jwh[t * 88 + d + KPS] = __float2half(ys[idx]);
                    }
                }
            } else {
                #pragma unroll
                for (int i = 0; i < 20; i++) {
                    int idx = lane + 32 * i;
                    if (idx < 624) {
                        int t = idx / KPS, d = idx - t * KPS;
                        bool ok = (gt0w + t) < ntok;
                        jwh[t * 88 + d]       = __float2half(ok ? xs[idx] : 0.f);
                        jwh[t * 88 + d + KPS] = __float2half(ok ? ys[idx] : 0.f);
                    }
                }
            }
        }
        __syncwarp();

        // ================= GEMM1: C[16tok x 200], 5 k-tiles ============
        float acc[25][4];
        #pragma unroll
        for (int nt = 0; nt < 25; nt++)
            #pragma unroll
            for (int i = 0; i < 4; i++) acc[nt][i] = 0.f;

        {
            const unsigned* ar0 = jwu + r * JH_U + tig;
            const unsigned* ar1 = ar0 + 8 * JH_U;
            #pragma unroll
            for (int kt = 0; kt < 5; kt++) {
                unsigned a0 = ar0[kt * 8];
                unsigned a1f = ar1[kt * 8];
                unsigned a2 = ar0[kt * 8 + 4];
                unsigned a3 = ar1[kt * 8 + 4];
                const float4* bp = (const float4*)ws + kt * 400 + lane;
                #pragma unroll
                for (int p = 0; p < 12; p++) {
                    float4 b = bp[p * 32];
                    mma_f16(acc[2*p],   a0, a1f, a2, a3,
                            __float_as_uint(b.x), __float_as_uint(b.y));
                    mma_f16(acc[2*p+1], a0, a1f, a2, a3,
                            __float_as_uint(b.z), __float_as_uint(b.w));
                }
                const uint2 bsg = *(const uint2*)(ws + kt * 1600 + 1536 + lane * 2);
                mma_f16(acc[24], a0, a1f, a2, a3, bsg.x, bsg.y);
            }
        }

        // ======== bias + PReLU + LN1 stats =============================
        float m0, m1, rs0, rs1;
        {
            float s0 = 0.f, q0 = 0.f, s1 = 0.f, q1 = 0.f;
            #pragma unroll
            for (int nt = 0; nt < 25; nt++) {
                int f0 = nt * 8 + 2 * tig;
                float2 bb = *(const float2*)&b1s[f0];
                float v;
                v = acc[nt][0] + bb.x; v = (v >= 0.f) ? v : a1v * v; if (f0     >= DHID) v = 0.f;
                acc[nt][0] = v; s0 += v; q0 += v * v;
                v = acc[nt][1] + bb.y; v = (v >= 0.f) ? v : a1v * v; if (f0 + 1 >= DHID) v = 0.f;
                acc[nt][1] = v; s0 += v; q0 += v * v;
                v = acc[nt][2] + bb.x; v = (v >= 0.f) ? v : a1v * v; if (f0     >= DHID) v = 0.f;
                acc[nt][2] = v; s1 += v; q1 += v * v;
                v = acc[nt][3] + bb.y; v = (v >= 0.f) ? v : a1v * v; if (f0 + 1 >= DHID) v = 0.f;
                acc[nt][3] = v; s1 += v; q1 += v * v;
            }
            s0 += __shfl_xor_sync(0xffffffffu, s0, 1); q0 += __shfl_xor_sync(0xffffffffu, q0, 1);
            s1 += __shfl_xor_sync(0xffffffffu, s1, 1); q1 += __shfl_xor_sync(0xffffffffu, q1, 1);
            s0 += __shfl_xor_sync(0xffffffffu, s0, 2); q0 += __shfl_xor_sync(0xffffffffu, q0, 2);
            s1 += __shfl_xor_sync(0xffffffffu, s1, 2); q1 += __shfl_xor_sync(0xffffffffu, q1, 2);
            m0 = s0 * (1.f / DHID); m1 = s1 * (1.f / DHID);
            rs0 = rsqrtf(q0 * (1.f / DHID) - m0 * m0 + 1e-5f);
            rs1 = rsqrtf(q1 * (1.f / DHID) - m1 * m1 + 1e-5f);
        }

        // ======== LN1 apply + pack to A-fragments (C==A layout) ========
        unsigned ah[25][2];
        #pragma unroll
        for (int nt = 0; nt < 25; nt++) {
            int f0 = nt * 8 + 2 * tig;
            float2 aa = albe1[f0];
            float2 ab = albe1[f0 + 1];
            ah[nt][0] = pack_h2((acc[nt][0] - m0) * rs0 * aa.x + aa.y,
                                (acc[nt][1] - m0) * rs0 * ab.x + ab.y);
            ah[nt][1] = pack_h2((acc[nt][2] - m1) * rs1 * aa.x + aa.y,
                                (acc[nt][3] - m1) * rs1 * ab.x + ab.y);
        }

        // ================= GEMM2: C[16tok x 80], 13 k-tiles ============
        float acc2[10][4];
        #pragma unroll
        for (int nt = 0; nt < 10; nt++)
            #pragma unroll
            for (int i = 0; i < 4; i++) acc2[nt][i] = 0.f;

        {
            #pragma unroll
            for (int kt = 0; kt < 13; kt++) {
                unsigned a0, a1f, a2, a3;
                if (kt < 12) {
                    a0 = ah[2*kt][0];   a1f = ah[2*kt][1];
                    a2 = ah[2*kt+1][0]; a3  = ah[2*kt+1][1];
                } else {
                    a0 = ah[24][0]; a1f = ah[24][1]; a2 = 0u; a3 = 0u;
                }
                const float4* bp = (const float4*)w2s + kt * 160 + lane;
                #pragma unroll
                for (int p = 0; p < 5; p++) {
                    float4 b = bp[p * 32];
                    mma_f16(acc2[2*p],   a0, a1f, a2, a3,
                            __float_as_uint(b.x), __float_as_uint(b.y));
                    mma_f16(acc2[2*p+1], a0, a1f, a2, a3,
                            __float_as_uint(b.z), __float_as_uint(b.w));
                }
            }
        }

        // ======== bias + PReLU + LN2 stats =============================
        float m0b, m1b, r0b, r1b;
        {
            float s0 = 0.f, q0 = 0.f, s1 = 0.f, q1 = 0.f;
            #pragma unroll
            for (int nt = 0; nt < 10; nt++) {
                int f0 = nt * 8 + 2 * tig;
                float2 bb = *(const float2*)&b2s[f0];
                float v;
                v = acc2[nt][0] + bb.x; v = (v >= 0.f) ? v : a2v * v; if (f0     >= DIN) v = 0.f;
                acc2[nt][0] = v; s0 += v; q0 += v * v;
                v = acc2[nt][1] + bb.y; v = (v >= 0.f) ? v : a2v * v; if (f0 + 1 >= DIN) v = 0.f;
                acc2[nt][1] = v; s0 += v; q0 += v * v;
                v = acc2[nt][2] + bb.x; v = (v >= 0.f) ? v : a2v * v; if (f0     >= DIN) v = 0.f;
                acc2[nt][2] = v; s1 += v; q1 += v * v;
                v = acc2[nt][3] + bb.y; v = (v >= 0.f) ? v : a2v * v; if (f0 + 1 >= DIN) v = 0.f;
                acc2[nt][3] = v; s1 += v; q1 += v * v;
            }
            s0 += __shfl_xor_sync(0xffffffffu, s0, 1); q0 += __shfl_xor_sync(0xffffffffu, q0, 1);
            s1 += __shfl_xor_sync(0xffffffffu, s1, 1); q1 += __shfl_xor_sync(0xffffffffu, q1, 1);
            s0 += __shfl_xor_sync(0xffffffffu, s0, 2); q0 += __shfl_xor_sync(0xffffffffu, q0, 2);
            s1 += __shfl_xor_sync(0xffffffffu, s1, 2); q1 += __shfl_xor_sync(0xffffffffu, q1, 2);
            m0b = s0 * (1.f / DIN); m1b = s1 * (1.f / DIN);
            r0b = rsqrtf(q0 * (1.f / DIN) - m0b * m0b + 1e-5f);
            r1b = rsqrtf(q1 * (1.f / DIN) - m1b * m1b + 1e-5f);
        }

        // ======== staged epilogue: two row-half passes through smem ====
        const size_t yofs = (size_t)ntok * KPS;
        #pragma unroll
        for (int half = 0; half < 2; half++) {
            const float mb = half ? m1b : m0b;
            const float rb = half ? r1b : r0b;
            __syncwarp();
            // normalize + scatter into slab: one STS.64 per nt, padded stride
            #pragma unroll
            for (int nt = 0; nt < 10; nt++) {
                int f0 = nt * 8 + 2 * tig;
                float2 aa = albe2[f0];
                float2 ab = albe2[f0 + 1];
                float c0 = half ? acc2[nt][2] : acc2[nt][0];
                float c1 = half ? acc2[nt][3] : acc2[nt][1];
                float2 o2;
                o2.x = (c0 - mb) * rb * aa.x + aa.y;
                o2.y = (c1 - mb) * rb * ab.x + ab.y;
                *(float2*)&oslw[r * OSL_S + f0] = o2;
            }
            __syncwarp();
            // coalesced drain: 8 tokens x 78 features, residual from gmem,
            // streaming stores (out is never re-read)
            const int t0 = gt0w + half * 8;
            const float* xs = x   + (size_t)t0 * KPS;
            const float* ys = y   + (size_t)t0 * KPS;
            float*       ox = out + (size_t)t0 * KPS;
            float*       oy = out + yofs + (size_t)t0 * KPS;
            if (t0 + 8 <= ntok) {
                #pragma unroll
                for (int i = 0; i < 20; i++) {
                    int idx = lane + 32 * i;
                    if (idx < 624) {
                        int t = idx / DIN, f = idx - t * DIN;
                        float v = oslw[t * OSL_S + f];
                        if (f < KPS) __stcs(&ox[t * KPS + f],       v + xs[t * KPS + f]);
                        else         __stcs(&oy[t * KPS + f - KPS], v + ys[t * KPS + f - KPS]);
                    }
                }
            } else {
                #pragma unroll
                for (int i = 0; i < 20; i++) {
                    int idx = lane + 32 * i;
                    if (idx < 624) {
                        int t = idx / DIN, f = idx - t * DIN;
                        if (t0 + t < ntok) {
                            float v = oslw[t * OSL_S + f];
                            if (f < KPS) __stcs(&ox[t * KPS + f],       v + xs[t * KPS + f]);
                            else         __stcs(&oy[t * KPS + f - KPS], v + ys[t * KPS + f - KPS]);
                        }
                    }
                }
            }
        }
    }
}

extern "C" void kernel_launch(void* const* d_in, const int* in_sizes, int n_in,
                              void* d_out, int out_size) {
    const float* x      = (const float*)d_in[0];
    const float* y      = (const float*)d_in[1];
    const float* W1     = (const float*)d_in[2];
    const float* b1     = (const float*)d_in[3];
    const float* W2     = (const float*)d_in[4];
    const float* b2     = (const float*)d_in[5];
    const float* a1     = (const float*)d_in[6];
    const float* a2     = (const float*)d_in[7];
    const float* alpha1 = (const float*)d_in[8];
    const float* beta1  = (const float*)d_in[9];
    const float* alpha2 = (const float*)d_in[10];
    const float* beta2  = (const float*)d_in[11];
    float* out = (float*)d_out;

    int ntok   = in_sizes[0] / KPS;
    int ntiles = (ntok + TB - 1) / TB;

    int dev = 0, nsm = 148;
    cudaGetDevice(&dev);
    cudaDeviceGetAttribute(&nsm, cudaDevAttrMultiProcessorCount, dev);
    int grid = 2 * nsm;
    if (grid > ntiles) grid = ntiles;

    size_t smem = SMEM_WORDS * sizeof(unsigned);

    prep_weights_kernel<<<64, 256>>>(W1, W2);

    cudaFuncSetAttribute(spatialctx_tc_kernel,
                         cudaFuncAttributeMaxDynamicSharedMemorySize, (int)smem);
    spatialctx_tc_kernel<<<grid, NT, smem>>>(
        x, y, b1, b2, a1, a2, alpha1, beta1, alpha2, beta2, out, ntok, ntiles);
}

// round 16
// speedup vs baseline: 1.6691x; 1.4675x over previous
#include <cuda_runtime.h>
#include <cuda_fp16.h>

#define KPS   39
#define DIN   78
#define DHID  195
#define TB    128      // tokens per tile
#define NT    256      // 8 warps, 16 tokens each

// uint offsets into dynamic smem
#define OFS_WS    0        // w1h frags 8000 u
#define OFS_W2    8000     // w2h frags 8320 u
#define OFS_JH    16320    // uint[128][44]  (= half[128][88]) : 5632 u
#define OFS_B1    21952    // 200 f
#define OFS_ALBE1 22152    // 400 f
#define OFS_B2    22552    // 80 f
#define OFS_ALBE2 22632    // 160 f
#define OFS_OSL   22792    // out slab: 8 warps x 8 rows x 84 f = 5376 f
#define SMEM_WORDS 28168   // 112672 bytes -> 2 CTAs/SM

#define JH_U  44           // uint stride per token row (88 halves)
#define OSL_S 84           // slab row stride (floats)

// fp16 weight fragment scratch (prepped once per launch), uint = fp16x2
__device__ unsigned g_w1h[8000];   // per kt(5): 12 nt-pairs [p][lane][4] + nt=24 [lane][2]
__device__ unsigned g_w2h[8320];   // per kt(13): 5 nt-pairs [p][lane][4]

__device__ __forceinline__ void mma_f16(float c[4],
                                        unsigned a0, unsigned a1, unsigned a2, unsigned a3,
                                        unsigned b0, unsigned b1) {
    asm volatile(
        "mma.sync.aligned.m16n8k16.row.col.f32.f16.f16.f32 "
        "{%0,%1,%2,%3}, {%4,%5,%6,%7}, {%8,%9}, {%0,%1,%2,%3};"
        : "+f"(c[0]), "+f"(c[1]), "+f"(c[2]), "+f"(c[3])
        : "r"(a0), "r"(a1), "r"(a2), "r"(a3), "r"(b0), "r"(b1));
}

__device__ __forceinline__ unsigned pack_h2(float lo, float hi) {
    __half2 h = __floats2half2_rn(lo, hi);
    return *(unsigned*)&h;
}

// ---------- prep: fp16-pack weights into mma fragment layout ----------
__global__ void prep_weights_kernel(const float* __restrict__ W1,
                                    const float* __restrict__ W2)
{
    int o = blockIdx.x * 256 + threadIdx.x;       // 0..16319
    if (o < 8000) {
        int kt  = o / 1600;
        int rem = o - kt * 1600;
        int n, kbase;
        if (rem < 1536) {
            int p    = rem >> 7;
            int q    = rem & 127;
            int lane = q >> 2, fi = q & 3;
            int gid = lane >> 2, tig = lane & 3;
            int nt  = 2 * p + (fi >> 1);
            n = nt * 8 + gid;
            kbase = kt * 16 + 2 * tig + 8 * (fi & 1);
        } else {
            int q    = rem - 1536;
            int lane = q >> 1, reg = q & 1;
            int gid = lane >> 2, tig = lane & 3;
            n = 192 + gid;
            kbase = kt * 16 + 2 * tig + 8 * reg;
        }
        float lo = (n < DHID && kbase     < DIN) ? W1[n * DIN + kbase]     : 0.f;
        float hi = (n < DHID && kbase + 1 < DIN) ? W1[n * DIN + kbase + 1] : 0.f;
        g_w1h[o] = pack_h2(lo, hi);
    } else if (o < 16320) {
        int o2  = o - 8000;
        int kt  = o2 / 640;
        int rem = o2 - kt * 640;
        int p    = rem >> 7;
        int q    = rem & 127;
        int lane = q >> 2, fi = q & 3;
        int gid = lane >> 2, tig = lane & 3;
        int nt  = 2 * p + (fi >> 1);
        int n = nt * 8 + gid;
        int kbase = kt * 16 + 2 * tig + 8 * (fi & 1);
        float lo = (n < DIN && kbase     < DHID) ? W2[n * DHID + kbase]     : 0.f;
        float hi = (n < DIN && kbase + 1 < DHID) ? W2[n * DHID + kbase + 1] : 0.f;
        g_w2h[o2] = pack_h2(lo, hi);
    }
}

// --------------------------------- main (persistent) ---------------------------------
__global__ __launch_bounds__(NT, 2)
void spatialctx_tc_kernel(
    const float* __restrict__ x, const float* __restrict__ y,
    const float* __restrict__ b1, const float* __restrict__ b2,
    const float* __restrict__ a1, const float* __restrict__ a2,
    const float* __restrict__ alpha1, const float* __restrict__ beta1,
    const float* __restrict__ alpha2, const float* __restrict__ beta2,
    float* __restrict__ out, int ntok, int ntiles)
{
    extern __shared__ unsigned smu[];
    unsigned* ws    = smu + OFS_WS;
    unsigned* w2s   = smu + OFS_W2;
    unsigned* jh    = smu + OFS_JH;
    float*    b1s   = (float*)(smu + OFS_B1);
    float2*   albe1 = (float2*)(smu + OFS_ALBE1);
    float*    b2s   = (float*)(smu + OFS_B2);
    float2*   albe2 = (float2*)(smu + OFS_ALBE2);
    float*    osl   = (float*)(smu + OFS_OSL);

    const int tid = threadIdx.x;

    // ---- prologue: stage both weight-fragment sets (once) ----
    {
        const float4* s1 = (const float4*)g_w1h;
        float4* d1 = (float4*)ws;
        #pragma unroll
        for (int i = 0; i < 8; i++) {
            int o = tid + i * NT;
            if (o < 2000) d1[o] = s1[o];
        }
        const float4* s2 = (const float4*)g_w2h;
        float4* d2 = (float4*)w2s;
        #pragma unroll
        for (int i = 0; i < 9; i++) {
            int o = tid + i * NT;
            if (o < 2080) d2[o] = s2[o];
        }
    }
    if (tid < 200) {
        b1s[tid] = (tid < DHID) ? b1[tid] : 0.f;
        albe1[tid] = make_float2((tid < DHID) ? alpha1[tid] : 0.f,
                                 (tid < DHID) ? beta1[tid]  : 0.f);
    }
    if (tid < 80) {
        b2s[tid] = (tid < DIN) ? b2[tid] : 0.f;
        albe2[tid] = make_float2((tid < DIN) ? alpha2[tid] : 0.f,
                                 (tid < DIN) ? beta2[tid]  : 0.f);
    }
    if (tid < 128) {       // zero the jh pad columns (halves 78..87) once
        #pragma unroll
        for (int c = 39; c < 44; c++) jh[tid * JH_U + c] = 0u;
    }
    const float a1v = a1[0];
    const float a2v = a2[0];
    __syncthreads();       // the only block-wide barrier

    const int warp   = tid >> 5;
    const int lane   = tid & 31;
    const int r      = lane >> 2;
    const int tig    = lane & 3;
    const int tokrow = warp * 16;

    unsigned* jwu  = jh + tokrow * JH_U;            // warp-private rows
    __half*   jwh  = (__half*)jwu;
    float*    oslw = osl + warp * (8 * OSL_S);      // warp-private 8x84 slab

    for (int tile = blockIdx.x; tile < ntiles; tile += gridDim.x) {
        const int tbase = tile * TB;
        const int gt0w  = tbase + tokrow;          // warp's first token

        // ---- stage warp's 16 token rows: x,y slabs are contiguous ----
        __syncwarp();
        {
            const float* xs = x + (size_t)gt0w * KPS;
            const float* ys = y + (size_t)gt0w * KPS;
            if (gt0w + 16 <= ntok) {
                #pragma unroll
                for (int i = 0; i < 20; i++) {
                    int idx = lane + 32 * i;
                    if (idx < 624) {
                        int t = idx / KPS, d = idx - t * KPS;
                        jwh[t * 88 + d]       = __float2half(xs[idx]);
                        jwh[t * 88 + d + KPS] = __float2half(ys[idx]);
                    }
                }
            } else {
                #pragma unroll
                for (int i = 0; i < 20; i++) {
                    int idx = lane + 32 * i;
                    if (idx < 624) {
                        int t = idx / KPS, d = idx - t * KPS;
                        bool ok = (gt0w + t) < ntok;
                        jwh[t * 88 + d]       = __float2half(ok ? xs[idx] : 0.f);
                        jwh[t * 88 + d + KPS] = __float2half(ok ? ys[idx] : 0.f);
                    }
                }
            }
        }
        __syncwarp();

        // ================= GEMM1: C[16tok x 200], 5 k-tiles ============
        float acc[25][4];
        #pragma unroll
        for (int nt = 0; nt < 25; nt++)
            #pragma unroll
            for (int i = 0; i < 4; i++) acc[nt][i] = 0.f;

        {
            const unsigned* ar0 = jwu + r * JH_U + tig;
            const unsigned* ar1 = ar0 + 8 * JH_U;
            #pragma unroll
            for (int kt = 0; kt < 5; kt++) {
                unsigned a0 = ar0[kt * 8];
                unsigned a1f = ar1[kt * 8];
                unsigned a2 = ar0[kt * 8 + 4];
                unsigned a3 = ar1[kt * 8 + 4];
                const float4* bp = (const float4*)ws + kt * 400 + lane;
                #pragma unroll
                for (int p = 0; p < 12; p++) {
                    float4 b = bp[p * 32];
                    mma_f16(acc[2*p],   a0, a1f, a2, a3,
                            __float_as_uint(b.x), __float_as_uint(b.y));
                    mma_f16(acc[2*p+1], a0, a1f, a2, a3,
                            __float_as_uint(b.z), __float_as_uint(b.w));
                }
                const uint2 bsg = *(const uint2*)(ws + kt * 1600 + 1536 + lane * 2);
                mma_f16(acc[24], a0, a1f, a2, a3, bsg.x, bsg.y);
            }
        }

        // ======== bias + PReLU + LN1 stats =============================
        float m0, m1, rs0, rs1;
        {
            float s0 = 0.f, q0 = 0.f, s1 = 0.f, q1 = 0.f;
            #pragma unroll
            for (int nt = 0; nt < 25; nt++) {
                int f0 = nt * 8 + 2 * tig;
                float2 bb = *(const float2*)&b1s[f0];
                float v;
                v = acc[nt][0] + bb.x; v = (v >= 0.f) ? v : a1v * v; if (f0     >= DHID) v = 0.f;
                acc[nt][0] = v; s0 += v; q0 += v * v;
                v = acc[nt][1] + bb.y; v = (v >= 0.f) ? v : a1v * v; if (f0 + 1 >= DHID) v = 0.f;
                acc[nt][1] = v; s0 += v; q0 += v * v;
                v = acc[nt][2] + bb.x; v = (v >= 0.f) ? v : a1v * v; if (f0     >= DHID) v = 0.f;
                acc[nt][2] = v; s1 += v; q1 += v * v;
                v = acc[nt][3] + bb.y; v = (v >= 0.f) ? v : a1v * v; if (f0 + 1 >= DHID) v = 0.f;
                acc[nt][3] = v; s1 += v; q1 += v * v;
            }
            s0 += __shfl_xor_sync(0xffffffffu, s0, 1); q0 += __shfl_xor_sync(0xffffffffu, q0, 1);
            s1 += __shfl_xor_sync(0xffffffffu, s1, 1); q1 += __shfl_xor_sync(0xffffffffu, q1, 1);
            s0 += __shfl_xor_sync(0xffffffffu, s0, 2); q0 += __shfl_xor_sync(0xffffffffu, q0, 2);
            s1 += __shfl_xor_sync(0xffffffffu, s1, 2); q1 += __shfl_xor_sync(0xffffffffu, q1, 2);
            m0 = s0 * (1.f / DHID); m1 = s1 * (1.f / DHID);
            rs0 = rsqrtf(q0 * (1.f / DHID) - m0 * m0 + 1e-5f);
            rs1 = rsqrtf(q1 * (1.f / DHID) - m1 * m1 + 1e-5f);
        }

        // ======== LN1 apply + pack to A-fragments (C==A layout) ========
        unsigned ah[25][2];
        #pragma unroll
        for (int nt = 0; nt < 25; nt++) {
            int f0 = nt * 8 + 2 * tig;
            float2 aa = albe1[f0];
            float2 ab = albe1[f0 + 1];
            ah[nt][0] = pack_h2((acc[nt][0] - m0) * rs0 * aa.x + aa.y,
                                (acc[nt][1] - m0) * rs0 * ab.x + ab.y);
            ah[nt][1] = pack_h2((acc[nt][2] - m1) * rs1 * aa.x + aa.y,
                                (acc[nt][3] - m1) * rs1 * ab.x + ab.y);
        }

        // ================= GEMM2: C[16tok x 80], 13 k-tiles ============
        float acc2[10][4];
        #pragma unroll
        for (int nt = 0; nt < 10; nt++)
            #pragma unroll
            for (int i = 0; i < 4; i++) acc2[nt][i] = 0.f;

        {
            #pragma unroll
            for (int kt = 0; kt < 13; kt++) {
                unsigned a0, a1f, a2, a3;
                if (kt < 12) {
                    a0 = ah[2*kt][0];   a1f = ah[2*kt][1];
                    a2 = ah[2*kt+1][0]; a3  = ah[2*kt+1][1];
                } else {
                    a0 = ah[24][0]; a1f = ah[24][1]; a2 = 0u; a3 = 0u;
                }
                const float4* bp = (const float4*)w2s + kt * 160 + lane;
                #pragma unroll
                for (int p = 0; p < 5; p++) {
                    float4 b = bp[p * 32];
                    mma_f16(acc2[2*p],   a0, a1f, a2, a3,
                            __float_as_uint(b.x), __float_as_uint(b.y));
                    mma_f16(acc2[2*p+1], a0, a1f, a2, a3,
                            __float_as_uint(b.z), __float_as_uint(b.w));
                }
            }
        }

        // ======== bias + PReLU + LN2 stats =============================
        float m0b, m1b, r0b, r1b;
        {
            float s0 = 0.f, q0 = 0.f, s1 = 0.f, q1 = 0.f;
            #pragma unroll
            for (int nt = 0; nt < 10; nt++) {
                int f0 = nt * 8 + 2 * tig;
                float2 bb = *(const float2*)&b2s[f0];
                float v;
                v = acc2[nt][0] + bb.x; v = (v >= 0.f) ? v : a2v * v; if (f0     >= DIN) v = 0.f;
                acc2[nt][0] = v; s0 += v; q0 += v * v;
                v = acc2[nt][1] + bb.y; v = (v >= 0.f) ? v : a2v * v; if (f0 + 1 >= DIN) v = 0.f;
                acc2[nt][1] = v; s0 += v; q0 += v * v;
                v = acc2[nt][2] + bb.x; v = (v >= 0.f) ? v : a2v * v; if (f0     >= DIN) v = 0.f;
                acc2[nt][2] = v; s1 += v; q1 += v * v;
                v = acc2[nt][3] + bb.y; v = (v >= 0.f) ? v : a2v * v; if (f0 + 1 >= DIN) v = 0.f;
                acc2[nt][3] = v; s1 += v; q1 += v * v;
            }
            s0 += __shfl_xor_sync(0xffffffffu, s0, 1); q0 += __shfl_xor_sync(0xffffffffu, q0, 1);
            s1 += __shfl_xor_sync(0xffffffffu, s1, 1); q1 += __shfl_xor_sync(0xffffffffu, q1, 1);
            s0 += __shfl_xor_sync(0xffffffffu, s0, 2); q0 += __shfl_xor_sync(0xffffffffu, q0, 2);
            s1 += __shfl_xor_sync(0xffffffffu, s1, 2); q1 += __shfl_xor_sync(0xffffffffu, q1, 2);
            m0b = s0 * (1.f / DIN); m1b = s1 * (1.f / DIN);
            r0b = rsqrtf(q0 * (1.f / DIN) - m0b * m0b + 1e-5f);
            r1b = rsqrtf(q1 * (1.f / DIN) - m1b * m1b + 1e-5f);
        }

        // ======== staged epilogue: two row-half passes through smem ====
        const size_t yofs = (size_t)ntok * KPS;
        #pragma unroll
        for (int half = 0; half < 2; half++) {
            const float mb = half ? m1b : m0b;
            const float rb = half ? r1b : r0b;
            __syncwarp();
            // normalize + scatter into slab: one STS.64 per nt, padded stride
            #pragma unroll
            for (int nt = 0; nt < 10; nt++) {
                int f0 = nt * 8 + 2 * tig;
                float2 aa = albe2[f0];
                float2 ab = albe2[f0 + 1];
                float c0 = half ? acc2[nt][2] : acc2[nt][0];
                float c1 = half ? acc2[nt][3] : acc2[nt][1];
                float2 o2;
                o2.x = (c0 - mb) * rb * aa.x + aa.y;
                o2.y = (c1 - mb) * rb * ab.x + ab.y;
                *(float2*)&oslw[r * OSL_S + f0] = o2;
            }
            __syncwarp();
            // coalesced drain: 8 tokens x 78 features, residual from gmem,
            // streaming stores (out is never re-read)
            const int t0 = gt0w + half * 8;
            const float* xs = x   + (size_t)t0 * KPS;
            const float* ys = y   + (size_t)t0 * KPS;
            float*       ox = out + (size_t)t0 * KPS;
            float*       oy = out + yofs + (size_t)t0 * KPS;
            if (t0 + 8 <= ntok) {
                #pragma unroll
                for (int i = 0; i < 20; i++) {
                    int idx = lane + 32 * i;
                    if (idx < 624) {
                        int t = idx / DIN, f = idx - t * DIN;
                        float v = oslw[t * OSL_S + f];
                        if (f < KPS) __stcs(&ox[t * KPS + f],       v + xs[t * KPS + f]);
                        else         __stcs(&oy[t * KPS + f - KPS], v + ys[t * KPS + f - KPS]);
                    }
                }
            } else {
                #pragma unroll
                for (int i = 0; i < 20; i++) {
                    int idx = lane + 32 * i;
                    if (idx < 624) {
                        int t = idx / DIN, f = idx - t * DIN;
                        if (t0 + t < ntok) {
                            float v = oslw[t * OSL_S + f];
                            if (f < KPS) __stcs(&ox[t * KPS + f],       v + xs[t * KPS + f]);
                            else         __stcs(&oy[t * KPS + f - KPS], v + ys[t * KPS + f - KPS]);
                        }
                    }
                }
            }
        }
    }
}

extern "C" void kernel_launch(void* const* d_in, const int* in_sizes, int n_in,
                              void* d_out, int out_size) {
    const float* x      = (const float*)d_in[0];
    const float* y      = (const float*)d_in[1];
    const float* W1     = (const float*)d_in[2];
    const float* b1     = (const float*)d_in[3];
    const float* W2     = (const float*)d_in[4];
    const float* b2     = (const float*)d_in[5];
    const float* a1     = (const float*)d_in[6];
    const float* a2     = (const float*)d_in[7];
    const float* alpha1 = (const float*)d_in[8];
    const float* beta1  = (const float*)d_in[9];
    const float* alpha2 = (const float*)d_in[10];
    const float* beta2  = (const float*)d_in[11];
    float* out = (float*)d_out;

    int ntok   = in_sizes[0] / KPS;
    int ntiles = (ntok + TB - 1) / TB;

    int dev = 0, nsm = 148;
    cudaGetDevice(&dev);
    cudaDeviceGetAttribute(&nsm, cudaDevAttrMultiProcessorCount, dev);
    int grid = 2 * nsm;
    if (grid > ntiles) grid = ntiles;

    size_t smem = SMEM_WORDS * sizeof(unsigned);

    prep_weights_kernel<<<64, 256>>>(W1, W2);

    cudaFuncSetAttribute(spatialctx_tc_kernel,
                         cudaFuncAttributeMaxDynamicSharedMemorySize, (int)smem);
    spatialctx_tc_kernel<<<grid, NT, smem>>>(
        x, y, b1, b2, a1, a2, alpha1, beta1, alpha2, beta2, out, ntok, ntiles);
}

// round 17
// speedup vs baseline: 1.7087x; 1.0237x over previous
#include <cuda_runtime.h>
#include <cuda_fp16.h>

#define KPS   39
#define DIN   78
#define DHID  195
#define TB    256      // tokens per tile
#define NT    512      // 16 warps, 16 tokens each  (ONE CTA per SM)

// uint offsets into dynamic smem
#define OFS_WS    0        // w1h frags 8000 u
#define OFS_W2    8000     // w2h frags 8320 u
#define OFS_JH    16320    // uint[256][44] : 11264 u
#define OFS_B1    27584    // 200 f
#define OFS_ALBE1 27784    // 400 f
#define OFS_B2    28184    // 80 f
#define OFS_ALBE2 28264    // 160 f
#define OFS_OSL   28424    // out slab: 16 warps x 8 rows x 84 f = 10752 f
#define SMEM_WORDS 39176   // 156704 bytes -> 1 CTA/SM, L1D ~71 KB

#define JH_U  44           // uint stride per token row (88 halves)
#define OSL_S 84           // slab row stride (floats)

// fp16 weight fragment scratch (prepped once per launch), uint = fp16x2
__device__ unsigned g_w1h[8000];   // per kt(5): 12 nt-pairs [p][lane][4] + nt=24 [lane][2]
__device__ unsigned g_w2h[8320];   // per kt(13): 5 nt-pairs [p][lane][4]

__device__ __forceinline__ void mma_f16(float c[4],
                                        unsigned a0, unsigned a1, unsigned a2, unsigned a3,
                                        unsigned b0, unsigned b1) {
    asm volatile(
        "mma.sync.aligned.m16n8k16.row.col.f32.f16.f16.f32 "
        "{%0,%1,%2,%3}, {%4,%5,%6,%7}, {%8,%9}, {%0,%1,%2,%3};"
        : "+f"(c[0]), "+f"(c[1]), "+f"(c[2]), "+f"(c[3])
        : "r"(a0), "r"(a1), "r"(a2), "r"(a3), "r"(b0), "r"(b1));
}

__device__ __forceinline__ unsigned pack_h2(float lo, float hi) {
    __half2 h = __floats2half2_rn(lo, hi);
    return *(unsigned*)&h;
}

// ---------- prep: fp16-pack weights into mma fragment layout ----------
__global__ void prep_weights_kernel(const float* __restrict__ W1,
                                    const float* __restrict__ W2)
{
    int o = blockIdx.x * 256 + threadIdx.x;       // 0..16319
    if (o < 8000) {
        int kt  = o / 1600;
        int rem = o - kt * 1600;
        int n, kbase;
        if (rem < 1536) {
            int p    = rem >> 7;
            int q    = rem & 127;
            int lane = q >> 2, fi = q & 3;
            int gid = lane >> 2, tig = lane & 3;
            int nt  = 2 * p + (fi >> 1);
            n = nt * 8 + gid;
            kbase = kt * 16 + 2 * tig + 8 * (fi & 1);
        } else {
            int q    = rem - 1536;
            int lane = q >> 1, reg = q & 1;
            int gid = lane >> 2, tig = lane & 3;
            n = 192 + gid;
            kbase = kt * 16 + 2 * tig + 8 * reg;
        }
        float lo = (n < DHID && kbase     < DIN) ? W1[n * DIN + kbase]     : 0.f;
        float hi = (n < DHID && kbase + 1 < DIN) ? W1[n * DIN + kbase + 1] : 0.f;
        g_w1h[o] = pack_h2(lo, hi);
    } else if (o < 16320) {
        int o2  = o - 8000;
        int kt  = o2 / 640;
        int rem = o2 - kt * 640;
        int p    = rem >> 7;
        int q    = rem & 127;
        int lane = q >> 2, fi = q & 3;
        int gid = lane >> 2, tig = lane & 3;
        int nt  = 2 * p + (fi >> 1);
        int n = nt * 8 + gid;
        int kbase = kt * 16 + 2 * tig + 8 * (fi & 1);
        float lo = (n < DIN && kbase     < DHID) ? W2[n * DHID + kbase]     : 0.f;
        float hi = (n < DIN && kbase + 1 < DHID) ? W2[n * DHID + kbase + 1] : 0.f;
        g_w2h[o2] = pack_h2(lo, hi);
    }
}

// --------------------------------- main (persistent, 1 CTA/SM) ---------------------------------
__global__ __launch_bounds__(NT, 1)
void spatialctx_tc_kernel(
    const float* __restrict__ x, const float* __restrict__ y,
    const float* __restrict__ b1, const float* __restrict__ b2,
    const float* __restrict__ a1, const float* __restrict__ a2,
    const float* __restrict__ alpha1, const float* __restrict__ beta1,
    const float* __restrict__ alpha2, const float* __restrict__ beta2,
    float* __restrict__ out, int ntok, int ntiles)
{
    extern __shared__ unsigned smu[];
    unsigned* ws    = smu + OFS_WS;
    unsigned* w2s   = smu + OFS_W2;
    unsigned* jh    = smu + OFS_JH;
    float*    b1s   = (float*)(smu + OFS_B1);
    float2*   albe1 = (float2*)(smu + OFS_ALBE1);
    float*    b2s   = (float*)(smu + OFS_B2);
    float2*   albe2 = (float2*)(smu + OFS_ALBE2);
    float*    osl   = (float*)(smu + OFS_OSL);

    const int tid = threadIdx.x;

    // ---- prologue: stage both weight-fragment sets (once) ----
    {
        const float4* s1 = (const float4*)g_w1h;
        float4* d1 = (float4*)ws;
        #pragma unroll
        for (int i = 0; i < 4; i++) {
            int o = tid + i * NT;
            if (o < 2000) d1[o] = s1[o];
        }
        const float4* s2 = (const float4*)g_w2h;
        float4* d2 = (float4*)w2s;
        #pragma unroll
        for (int i = 0; i < 5; i++) {
            int o = tid + i * NT;
            if (o < 2080) d2[o] = s2[o];
        }
    }
    if (tid < 200) {
        b1s[tid] = (tid < DHID) ? b1[tid] : 0.f;
        albe1[tid] = make_float2((tid < DHID) ? alpha1[tid] : 0.f,
                                 (tid < DHID) ? beta1[tid]  : 0.f);
    }
    if (tid < 80) {
        b2s[tid] = (tid < DIN) ? b2[tid] : 0.f;
        albe2[tid] = make_float2((tid < DIN) ? alpha2[tid] : 0.f,
                                 (tid < DIN) ? beta2[tid]  : 0.f);
    }
    if (tid < 256) {       // zero the jh pad columns (halves 78..87) once
        #pragma unroll
        for (int c = 39; c < 44; c++) jh[tid * JH_U + c] = 0u;
    }
    const float a1v = a1[0];
    const float a2v = a2[0];
    __syncthreads();       // the only block-wide barrier

    const int warp   = tid >> 5;
    const int lane   = tid & 31;
    const int r      = lane >> 2;
    const int tig    = lane & 3;
    const int tokrow = warp * 16;

    unsigned* jwu  = jh + tokrow * JH_U;            // warp-private rows
    __half*   jwh  = (__half*)jwu;
    float*    oslw = osl + warp * (8 * OSL_S);      // warp-private 8x84 slab

    for (int tile = blockIdx.x; tile < ntiles; tile += gridDim.x) {
        const int tbase = tile * TB;
        const int gt0w  = tbase + tokrow;          // warp's first token

        // ---- stage warp's 16 token rows: x,y slabs are contiguous ----
        __syncwarp();
        {
            const float* xs = x + (size_t)gt0w * KPS;
            const float* ys = y + (size_t)gt0w * KPS;
            if (gt0w + 16 <= ntok) {
                #pragma unroll
                for (int i = 0; i < 20; i++) {
                    int idx = lane + 32 * i;
                    if (idx < 624) {
                        int t = idx / KPS, d = idx - t * KPS;
                        jwh[t * 88 + d]       = __float2half(xs[idx]);
                        jwh[t * 88 + d + KPS] = __float2half(ys[idx]);
                    }
                }
            } else {
                #pragma unroll
                for (int i = 0; i < 20; i++) {
                    int idx = lane + 32 * i;
                    if (idx < 624) {
                        int t = idx / KPS, d = idx - t * KPS;
                        bool ok = (gt0w + t) < ntok;
                        jwh[t * 88 + d]       = __float2half(ok ? xs[idx] : 0.f);
                        jwh[t * 88 + d + KPS] = __float2half(ok ? ys[idx] : 0.f);
                    }
                }
            }
        }
        __syncwarp();

        // ================= GEMM1: C[16tok x 200], 5 k-tiles ============
        float acc[25][4];
        #pragma unroll
        for (int nt = 0; nt < 25; nt++)
            #pragma unroll
            for (int i = 0; i < 4; i++) acc[nt][i] = 0.f;

        {
            const unsigned* ar0 = jwu + r * JH_U + tig;
            const unsigned* ar1 = ar0 + 8 * JH_U;
            #pragma unroll
            for (int kt = 0; kt < 5; kt++) {
                unsigned a0 = ar0[kt * 8];
                unsigned a1f = ar1[kt * 8];
                unsigned a2 = ar0[kt * 8 + 4];
                unsigned a3 = ar1[kt * 8 + 4];
                const float4* bp = (const float4*)ws + kt * 400 + lane;
                #pragma unroll
                for (int p = 0; p < 12; p++) {
                    float4 b = bp[p * 32];
                    mma_f16(acc[2*p],   a0, a1f, a2, a3,
                            __float_as_uint(b.x), __float_as_uint(b.y));
                    mma_f16(acc[2*p+1], a0, a1f, a2, a3,
                            __float_as_uint(b.z), __float_as_uint(b.w));
                }
                const uint2 bsg = *(const uint2*)(ws + kt * 1600 + 1536 + lane * 2);
                mma_f16(acc[24], a0, a1f, a2, a3, bsg.x, bsg.y);
            }
        }

        // ======== bias + PReLU + LN1 stats =============================
        float m0, m1, rs0, rs1;
        {
            float s0 = 0.f, q0 = 0.f, s1 = 0.f, q1 = 0.f;
            #pragma unroll
            for (int nt = 0; nt < 25; nt++) {
                int f0 = nt * 8 + 2 * tig;
                float2 bb = *(const float2*)&b1s[f0];
                float v;
                v = acc[nt][0] + bb.x; v = (v >= 0.f) ? v : a1v * v; if (f0     >= DHID) v = 0.f;
                acc[nt][0] = v; s0 += v; q0 += v * v;
                v = acc[nt][1] + bb.y; v = (v >= 0.f) ? v : a1v * v; if (f0 + 1 >= DHID) v = 0.f;
                acc[nt][1] = v; s0 += v; q0 += v * v;
                v = acc[nt][2] + bb.x; v = (v >= 0.f) ? v : a1v * v; if (f0     >= DHID) v = 0.f;
                acc[nt][2] = v; s1 += v; q1 += v * v;
                v = acc[nt][3] + bb.y; v = (v >= 0.f) ? v : a1v * v; if (f0 + 1 >= DHID) v = 0.f;
                acc[nt][3] = v; s1 += v; q1 += v * v;
            }
            s0 += __shfl_xor_sync(0xffffffffu, s0, 1); q0 += __shfl_xor_sync(0xffffffffu, q0, 1);
            s1 += __shfl_xor_sync(0xffffffffu, s1, 1); q1 += __shfl_xor_sync(0xffffffffu, q1, 1);
            s0 += __shfl_xor_sync(0xffffffffu, s0, 2); q0 += __shfl_xor_sync(0xffffffffu, q0, 2);
            s1 += __shfl_xor_sync(0xffffffffu, s1, 2); q1 += __shfl_xor_sync(0xffffffffu, q1, 2);
            m0 = s0 * (1.f / DHID); m1 = s1 * (1.f / DHID);
            rs0 = rsqrtf(q0 * (1.f / DHID) - m0 * m0 + 1e-5f);
            rs1 = rsqrtf(q1 * (1.f / DHID) - m1 * m1 + 1e-5f);
        }

        // ======== LN1 apply + pack to A-fragments (C==A layout) ========
        unsigned ah[25][2];
        #pragma unroll
        for (int nt = 0; nt < 25; nt++) {
            int f0 = nt * 8 + 2 * tig;
            float2 aa = albe1[f0];
            float2 ab = albe1[f0 + 1];
            ah[nt][0] = pack_h2((acc[nt][0] - m0) * rs0 * aa.x + aa.y,
                                (acc[nt][1] - m0) * rs0 * ab.x + ab.y);
            ah[nt][1] = pack_h2((acc[nt][2] - m1) * rs1 * aa.x + aa.y,
                                (acc[nt][3] - m1) * rs1 * ab.x + ab.y);
        }

        // ================= GEMM2: C[16tok x 80], 13 k-tiles ============
        float acc2[10][4];
        #pragma unroll
        for (int nt = 0; nt < 10; nt++)
            #pragma unroll
            for (int i = 0; i < 4; i++) acc2[nt][i] = 0.f;

        {
            #pragma unroll
            for (int kt = 0; kt < 13; kt++) {
                unsigned a0, a1f, a2, a3;
                if (kt < 12) {
                    a0 = ah[2*kt][0];   a1f = ah[2*kt][1];
                    a2 = ah[2*kt+1][0]; a3  = ah[2*kt+1][1];
                } else {
                    a0 = ah[24][0]; a1f = ah[24][1]; a2 = 0u; a3 = 0u;
                }
                const float4* bp = (const float4*)w2s + kt * 160 + lane;
                #pragma unroll
                for (int p = 0; p < 5; p++) {
                    float4 b = bp[p * 32];
                    mma_f16(acc2[2*p],   a0, a1f, a2, a3,
                            __float_as_uint(b.x), __float_as_uint(b.y));
                    mma_f16(acc2[2*p+1], a0, a1f, a2, a3,
                            __float_as_uint(b.z), __float_as_uint(b.w));
                }
            }
        }

        // ======== bias + PReLU + LN2 stats =============================
        float m0b, m1b, r0b, r1b;
        {
            float s0 = 0.f, q0 = 0.f, s1 = 0.f, q1 = 0.f;
            #pragma unroll
            for (int nt = 0; nt < 10; nt++) {
                int f0 = nt * 8 + 2 * tig;
                float2 bb = *(const float2*)&b2s[f0];
                float v;
                v = acc2[nt][0] + bb.x; v = (v >= 0.f) ? v : a2v * v; if (f0     >= DIN) v = 0.f;
                acc2[nt][0] = v; s0 += v; q0 += v * v;
                v = acc2[nt][1] + bb.y; v = (v >= 0.f) ? v : a2v * v; if (f0 + 1 >= DIN) v = 0.f;
                acc2[nt][1] = v; s0 += v; q0 += v * v;
                v = acc2[nt][2] + bb.x; v = (v >= 0.f) ? v : a2v * v; if (f0     >= DIN) v = 0.f;
                acc2[nt][2] = v; s1 += v; q1 += v * v;
                v = acc2[nt][3] + bb.y; v = (v >= 0.f) ? v : a2v * v; if (f0 + 1 >= DIN) v = 0.f;
                acc2[nt][3] = v; s1 += v; q1 += v * v;
            }
            s0 += __shfl_xor_sync(0xffffffffu, s0, 1); q0 += __shfl_xor_sync(0xffffffffu, q0, 1);
            s1 += __shfl_xor_sync(0xffffffffu, s1, 1); q1 += __shfl_xor_sync(0xffffffffu, q1, 1);
            s0 += __shfl_xor_sync(0xffffffffu, s0, 2); q0 += __shfl_xor_sync(0xffffffffu, q0, 2);
            s1 += __shfl_xor_sync(0xffffffffu, s1, 2); q1 += __shfl_xor_sync(0xffffffffu, q1, 2);
            m0b = s0 * (1.f / DIN); m1b = s1 * (1.f / DIN);
            r0b = rsqrtf(q0 * (1.f / DIN) - m0b * m0b + 1e-5f);
            r1b = rsqrtf(q1 * (1.f / DIN) - m1b * m1b + 1e-5f);
        }

        // ======== staged epilogue: two row-half passes through smem ====
        const size_t yofs = (size_t)ntok * KPS;
        #pragma unroll
        for (int half = 0; half < 2; half++) {
            const float mb = half ? m1b : m0b;
            const float rb = half ? r1b : r0b;
            __syncwarp();
            // normalize + scatter into slab: one STS.64 per nt, padded stride
            #pragma unroll
            for (int nt = 0; nt < 10; nt++) {
                int f0 = nt * 8 + 2 * tig;
                float2 aa = albe2[f0];
                float2 ab = albe2[f0 + 1];
                float c0 = half ? acc2[nt][2] : acc2[nt][0];
                float c1 = half ? acc2[nt][3] : acc2[nt][1];
                float2 o2;
                o2.x = (c0 - mb) * rb * aa.x + aa.y;
                o2.y = (c1 - mb) * rb * ab.x + ab.y;
                *(float2*)&oslw[r * OSL_S + f0] = o2;
            }
            __syncwarp();
            // coalesced drain: 8 tokens x 78 features, residual from gmem,
            // streaming stores (out is never re-read)
            const int t0 = gt0w + half * 8;
            const float* xs = x   + (size_t)t0 * KPS;
            const float* ys = y   + (size_t)t0 * KPS;
            float*       ox = out + (size_t)t0 * KPS;
            float*       oy = out + yofs + (size_t)t0 * KPS;
            if (t0 + 8 <= ntok) {
                #pragma unroll
                for (int i = 0; i < 20; i++) {
                    int idx = lane + 32 * i;
                    if (idx < 624) {
                        int t = idx / DIN, f = idx - t * DIN;
                        float v = oslw[t * OSL_S + f];
                        if (f < KPS) __stcs(&ox[t * KPS + f],       v + xs[t * KPS + f]);
                        else         __stcs(&oy[t * KPS + f - KPS], v + ys[t * KPS + f - KPS]);
                    }
                }
            } else {
                #pragma unroll
                for (int i = 0; i < 20; i++) {
                    int idx = lane + 32 * i;
                    if (idx < 624) {
                        int t = idx / DIN, f = idx - t * DIN;
                        if (t0 + t < ntok) {
                            float v = oslw[t * OSL_S + f];
                            if (f < KPS) __stcs(&ox[t * KPS + f],       v + xs[t * KPS + f]);
                            else         __stcs(&oy[t * KPS + f - KPS], v + ys[t * KPS + f - KPS]);
                        }
                    }
                }
            }
        }
    }
}

extern "C" void kernel_launch(void* const* d_in, const int* in_sizes, int n_in,
                              void* d_out, int out_size) {
    const float* x      = (const float*)d_in[0];
    const float* y      = (const float*)d_in[1];
    const float* W1     = (const float*)d_in[2];
    const float* b1     = (const float*)d_in[3];
    const float* W2     = (const float*)d_in[4];
    const float* b2     = (const float*)d_in[5];
    const float* a1     = (const float*)d_in[6];
    const float* a2     = (const float*)d_in[7];
    const float* alpha1 = (const float*)d_in[8];
    const float* beta1  = (const float*)d_in[9];
    const float* alpha2 = (const float*)d_in[10];
    const float* beta2  = (const float*)d_in[11];
    float* out = (float*)d_out;

    int ntok   = in_sizes[0] / KPS;
    int ntiles = (ntok + TB - 1) / TB;

    int dev = 0, nsm = 148;
    cudaGetDevice(&dev);
    cudaDeviceGetAttribute(&nsm, cudaDevAttrMultiProcessorCount, dev);
    int grid = nsm;
    if (grid > ntiles) grid = ntiles;

    size_t smem = SMEM_WORDS * sizeof(unsigned);

    prep_weights_kernel<<<64, 256>>>(W1, W2);

    cudaFuncSetAttribute(spatialctx_tc_kernel,
                         cudaFuncAttributeMaxDynamicSharedMemorySize, (int)smem);
    spatialctx_tc_kernel<<<grid, NT, smem>>>(
        x, y, b1, b2, a1, a2, alpha1, beta1, alpha2, beta2, out, ntok, ntiles);
}